// round 5
// baseline (speedup 1.0000x reference)
#include <cuda_runtime.h>
#include <cstdint>

// Problem constants
#define B_   16
#define C_   128
#define H_   128
#define W_   128
#define OUT_ 256
#define HW_  (H_ * W_)

#define YS_STRIDE 72   // words; 72 % 32 == 8 -> B-frag LDS conflict-free

// Pre-packed W in A-fragment order: [kstep 16][mtile 16][lane 32][word 4], tf32 bits.
//   word w, lane l -> W[mtile*16 + (w&1)*8 + (l>>2)][kstep*8 + (w>>1)*4 + (l&3)]
__device__ uint32_t g_AF[16 * 16 * 32 * 4];   // 128 KB, L1-resident during fused kernel

__device__ __forceinline__ uint32_t f2tf32(float f) {
    uint32_t u;
    asm("cvt.rna.tf32.f32 %0, %1;" : "=r"(u) : "f"(f));
    return u;
}

__device__ __forceinline__ void mma_tf32(float* d, const uint32_t* a, const uint32_t* b) {
    asm volatile(
        "mma.sync.aligned.m16n8k8.row.col.f32.tf32.tf32.f32 "
        "{%0,%1,%2,%3}, {%4,%5,%6,%7}, {%8,%9}, {%0,%1,%2,%3};"
        : "+f"(d[0]), "+f"(d[1]), "+f"(d[2]), "+f"(d[3])
        : "r"(a[0]), "r"(a[1]), "r"(a[2]), "r"(a[3]), "r"(b[0]), "r"(b[1]));
}

// ---------------------------------------------------------------------------
// Prep kernel: pack W (OUT x C, f32) into fragment-ordered tf32 image g_AF.
// ---------------------------------------------------------------------------
__global__ __launch_bounds__(512) void prep_kernel(const float* __restrict__ Wg) {
    const int idx   = blockIdx.x * 512 + threadIdx.x;   // 0..32767
    const int wrd   = idx & 3;
    const int lane  = (idx >> 2) & 31;
    const int mtile = (idx >> 7) & 15;
    const int kstep = idx >> 11;
    const int m = mtile * 16 + ((wrd & 1) << 3) + (lane >> 2);
    const int k = kstep * 8 + ((wrd >> 1) << 2) + (lane & 3);
    g_AF[idx] = f2tf32(Wg[m * C_ + k]);
}

// ---------------------------------------------------------------------------
// Fused kernel: one CTA per (b, h, pixel-half). 256 threads = 8 warps (4M x 2N).
//   Phase 1: depthwise-separable 3x3 for 128 channels x 64 pixels -> smem (tf32)
//   Phase 2: GEMM out[b, 0:256, h, p0:p0+64] = W(256x128) @ y(128x64)
//            A-fragments streamed from g_AF via LDG (L1-hit), B from smem.
// 2 CTAs co-resident per SM -> phases of different CTAs overlap.
// ---------------------------------------------------------------------------
__global__ __launch_bounds__(256, 2) void fused_kernel(
    const float* __restrict__ x,
    const float* __restrict__ colk,
    const float* __restrict__ rowk,
    float* __restrict__ out)
{
    __shared__ uint32_t Ys[C_ * YS_STRIDE];   // 36864 B

    const int tid  = threadIdx.x;
    const int lane = tid & 31;
    const int warp = tid >> 5;

    const int half = blockIdx.x & 1;
    const int h    = blockIdx.x >> 1;
    const int b    = blockIdx.y;
    const int p0   = half * 64;

    // ---------------- Phase 1: depthwise -> Ys ----------------
    // Warp handles 16 channels; each iteration covers 2 channels via 16-lane
    // segments (seg = lane>>4). Segment lanes cover 64 px (4 px each).
    {
        const unsigned FULL = 0xFFFFFFFFu;
        const int sl  = lane & 15;
        const int seg = lane >> 4;

        #pragma unroll
        for (int it = 0; it < 8; ++it) {
            const int c = warp * 16 + it * 2 + seg;
            const float r0 = rowk[c * 3 + 0], r1 = rowk[c * 3 + 1], r2 = rowk[c * 3 + 2];
            const float ck0 = colk[c * 3 + 0], ck1 = colk[c * 3 + 1], ck2 = colk[c * 3 + 2];
            const float* xc = x + ((size_t)(b * C_ + c) * H_) * W_;

            float y0 = 0.f, y1 = 0.f, y2 = 0.f, y3 = 0.f;
            #pragma unroll
            for (int dr = 0; dr < 3; ++dr) {
                const int row = h - 1 + dr;
                const bool rowOK = (row >= 0) && (row < H_);
                float4 v = make_float4(0.f, 0.f, 0.f, 0.f);
                if (rowOK)
                    v = *(const float4*)(xc + (size_t)row * W_ + p0 + sl * 4);
                float left  = __shfl_up_sync(FULL, v.w, 1, 16);
                float right = __shfl_down_sync(FULL, v.x, 1, 16);
                if (sl == 0)
                    left = (rowOK && p0 > 0) ? xc[(size_t)row * W_ + p0 - 1] : 0.f;
                if (sl == 15)
                    right = (rowOK && p0 + 64 < W_) ? xc[(size_t)row * W_ + p0 + 64] : 0.f;
                const float kc = (dr == 0) ? ck0 : (dr == 1) ? ck1 : ck2;
                y0 += kc * (r0 * left + r1 * v.x + r2 * v.y);
                y1 += kc * (r0 * v.x  + r1 * v.y + r2 * v.z);
                y2 += kc * (r0 * v.y  + r1 * v.z + r2 * v.w);
                y3 += kc * (r0 * v.z  + r1 * v.w + r2 * right);
            }
            uint4 ty;
            ty.x = f2tf32(y0); ty.y = f2tf32(y1); ty.z = f2tf32(y2); ty.w = f2tf32(y3);
            *(uint4*)&Ys[c * YS_STRIDE + sl * 4] = ty;
        }
    }
    __syncthreads();

    // ---------------- Phase 2: GEMM ----------------
    const int wm = warp >> 1;   // 0..3 -> M offset wm*64 (mtiles wm*4 .. wm*4+3)
    const int wn = warp & 1;    // 0..1 -> N offset wn*32

    float acc[4][4][4] = {};

    // A-frag stream: element index ((k*16 + wm*4+mt)*32 + lane)*4
    const uint32_t* AF = g_AF + ((size_t)(wm * 4) * 32 + lane) * 4;
    const int bfBase = (lane & 3) * YS_STRIDE + wn * 32 + (lane >> 2);

    #pragma unroll
    for (int k = 0; k < 16; ++k) {
        uint32_t a[4][4];
        uint32_t bf[4][2];
        #pragma unroll
        for (int mt = 0; mt < 4; ++mt)
            *(uint4*)a[mt] = __ldg((const uint4*)(AF + k * 2048 + mt * 128));
        #pragma unroll
        for (int nt = 0; nt < 4; ++nt) {
            bf[nt][0] = Ys[bfBase + k * 8 * YS_STRIDE + nt * 8];
            bf[nt][1] = Ys[bfBase + (k * 8 + 4) * YS_STRIDE + nt * 8];
        }
        #pragma unroll
        for (int mt = 0; mt < 4; ++mt)
            #pragma unroll
            for (int nt = 0; nt < 4; ++nt)
                mma_tf32(acc[mt][nt], a[mt], bf[nt]);
    }

    // ---------------- Epilogue ----------------
    float* ob = out + ((size_t)b * OUT_) * HW_ + (size_t)h * W_ + p0;
    #pragma unroll
    for (int mt = 0; mt < 4; ++mt) {
        int o0 = wm * 64 + mt * 16 + (lane >> 2);
        #pragma unroll
        for (int nt = 0; nt < 4; ++nt) {
            int p = wn * 32 + nt * 8 + (lane & 3) * 2;
            *(float2*)(ob + (size_t)o0 * HW_ + p) =
                make_float2(acc[mt][nt][0], acc[mt][nt][1]);
            *(float2*)(ob + (size_t)(o0 + 8) * HW_ + p) =
                make_float2(acc[mt][nt][2], acc[mt][nt][3]);
        }
    }
}

// ---------------------------------------------------------------------------
extern "C" void kernel_launch(void* const* d_in, const int* in_sizes, int n_in,
                              void* d_out, int out_size)
{
    (void)in_sizes; (void)n_in; (void)out_size;
    const float* x    = (const float*)d_in[0];
    const float* colk = (const float*)d_in[1];
    const float* rowk = (const float*)d_in[2];
    const float* pw   = (const float*)d_in[3];
    float* out = (float*)d_out;

    prep_kernel<<<64, 512>>>(pw);
    fused_kernel<<<dim3(H_ * 2, B_), 256>>>(x, colk, rowk, out);
}

// round 6
// speedup vs baseline: 1.9437x; 1.9437x over previous
#include <cuda_runtime.h>
#include <cuda_fp16.h>
#include <cstdint>

// Problem constants
#define B_   16
#define C_   128
#define H_   128
#define W_   128
#define OUT_ 256
#define HW_  (H_ * W_)

#define KSTR 136   // halves per Ys row (272 B); row bank offset = 4*row -> conflict-free ldmatrix

// Shared memory layout (bytes):
//  [0 : 34816)        Ys  half[128][136]
//  [34816 : 100352)   A fragments (fp16, packed), 64 KB
#define SMEM_YS_BYTES (C_ * KSTR * 2)        // 34816
#define SMEM_A        SMEM_YS_BYTES
#define SMEM_TOT      (SMEM_A + 65536)       // 100352

// Pre-packed W as fp16 A-fragments for mma.m16n8k16:
//   g_AF[kstep 8][mtile 16][lane 32][reg 4]  (uint32 = half2)
//   reg r, lane l -> rows m = mtile*16 + (l>>2) + (r&1)*8,
//                    cols k = kstep*16 + (l&3)*2 + (r>>1)*8, plus k+1 in high half
__device__ uint32_t g_AF[8 * 16 * 32 * 4];   // 64 KB

__device__ __forceinline__ uint32_t s2u(const void* p) {
    uint32_t a;
    asm("{ .reg .u64 t; cvta.to.shared.u64 t, %1; cvt.u32.u64 %0, t; }" : "=r"(a) : "l"(p));
    return a;
}

__device__ __forceinline__ void mma_f16(float* d, const uint32_t* a, const uint32_t* b) {
    asm volatile(
        "mma.sync.aligned.m16n8k16.row.col.f32.f16.f16.f32 "
        "{%0,%1,%2,%3}, {%4,%5,%6,%7}, {%8,%9}, {%0,%1,%2,%3};"
        : "+f"(d[0]), "+f"(d[1]), "+f"(d[2]), "+f"(d[3])
        : "r"(a[0]), "r"(a[1]), "r"(a[2]), "r"(a[3]), "r"(b[0]), "r"(b[1]));
}

// ---------------------------------------------------------------------------
// Prep kernel: pack W (OUT x C, f32) into fp16 fragment image g_AF.
// ---------------------------------------------------------------------------
__global__ __launch_bounds__(512) void prep_kernel(const float* __restrict__ Wg) {
    const int idx   = blockIdx.x * 512 + threadIdx.x;   // 0..16383
    const int r     = idx & 3;
    const int lane  = (idx >> 2) & 31;
    const int mtile = (idx >> 7) & 15;
    const int kstep = idx >> 11;
    const int m = mtile * 16 + (lane >> 2) + ((r & 1) << 3);
    const int k = kstep * 16 + ((lane & 3) << 1) + ((r >> 1) << 3);
    const __half2 h = __floats2half2_rn(Wg[m * C_ + k], Wg[m * C_ + k + 1]);
    g_AF[idx] = *(const uint32_t*)&h;
}

// ---------------------------------------------------------------------------
// Fused kernel: one CTA per (b, h) output row. 512 threads = 16 warps (4M x 4N).
//   Phase 0: cp.async of fp16 A-fragment image (64 KB) -> smem
//   Phase 1: depthwise-separable 3x3, 128 channels x 128 px -> Ys (fp16)
//   Phase 2: fp16 GEMM m16n8k16, B via ldmatrix.x4.trans, no interior barriers
// ---------------------------------------------------------------------------
__global__ __launch_bounds__(512, 1) void fused_kernel(
    const float* __restrict__ x,
    const float* __restrict__ colk,
    const float* __restrict__ rowk,
    float* __restrict__ out)
{
    extern __shared__ char smem[];
    const uint32_t sb = s2u(smem);

    const int tid  = threadIdx.x;
    const int lane = tid & 31;
    const int warp = tid >> 5;
    const int h    = blockIdx.x;
    const int b    = blockIdx.y;

    // ---------------- Phase 0: async copy of A-fragment image ----------------
    {
        const size_t gsrc = __cvta_generic_to_global(g_AF) + (size_t)tid * 16;
        const uint32_t dst = sb + SMEM_A + tid * 16;
        #pragma unroll
        for (int i = 0; i < 8; ++i) {
            asm volatile("cp.async.ca.shared.global [%0], [%1], 16;"
                         :: "r"(dst + i * 512 * 16), "l"(gsrc + (size_t)i * 512 * 16)
                         : "memory");
        }
        asm volatile("cp.async.commit_group;" ::: "memory");
    }

    // ---------------- Phase 1: depthwise -> Ys (fp16) ----------------
    {
        const unsigned FULL = 0xFFFFFFFFu;
        #pragma unroll
        for (int i = 0; i < 8; ++i) {
            const int c = warp * 8 + i;
            const float r0 = rowk[c * 3 + 0], r1 = rowk[c * 3 + 1], r2 = rowk[c * 3 + 2];
            const float ck0 = colk[c * 3 + 0], ck1 = colk[c * 3 + 1], ck2 = colk[c * 3 + 2];
            const float* xc = x + ((size_t)(b * C_ + c) * H_) * W_;

            float y0 = 0.f, y1 = 0.f, y2 = 0.f, y3 = 0.f;
            #pragma unroll
            for (int dr = 0; dr < 3; ++dr) {
                const int row = h - 1 + dr;
                float4 v = make_float4(0.f, 0.f, 0.f, 0.f);
                if (row >= 0 && row < H_)
                    v = *(const float4*)(xc + (size_t)row * W_ + lane * 4);
                float left  = __shfl_up_sync(FULL, v.w, 1);
                float right = __shfl_down_sync(FULL, v.x, 1);
                if (lane == 0)  left = 0.f;
                if (lane == 31) right = 0.f;
                const float kc = (dr == 0) ? ck0 : (dr == 1) ? ck1 : ck2;
                y0 += kc * (r0 * left + r1 * v.x + r2 * v.y);
                y1 += kc * (r0 * v.x  + r1 * v.y + r2 * v.z);
                y2 += kc * (r0 * v.y  + r1 * v.z + r2 * v.w);
                y3 += kc * (r0 * v.z  + r1 * v.w + r2 * right);
            }
            const __half2 h01 = __floats2half2_rn(y0, y1);
            const __half2 h23 = __floats2half2_rn(y2, y3);
            uint2 tw;
            tw.x = *(const uint32_t*)&h01;
            tw.y = *(const uint32_t*)&h23;
            *(uint2*)(smem + (size_t)c * (KSTR * 2) + lane * 8) = tw;
        }
    }

    asm volatile("cp.async.wait_group 0;" ::: "memory");
    __syncthreads();

    // ---------------- Phase 2: GEMM (no interior barriers) ----------------
    const int wm = warp >> 2;   // 0..3 -> M offset wm*64 (mtiles wm*4..wm*4+3)
    const int wn = warp & 3;    // 0..3 -> N offset wn*32

    float acc[4][4][4] = {};

    // A: LDS.128 from packed image; lane-major 16B -> conflict-free
    const uint32_t aBase = sb + SMEM_A + (uint32_t)(((wm * 4) * 32 + lane) * 16);
    // B: ldmatrix.x4.trans; tile t = lane>>3, row = lane&7
    const int bt   = lane >> 3;
    const int brow = lane & 7;

    #pragma unroll
    for (int k = 0; k < 8; ++k) {
        uint32_t a[4][4];
        #pragma unroll
        for (int mt = 0; mt < 4; ++mt) {
            const uint32_t addr = aBase + (uint32_t)(k * 16 * 512 + mt * 512);
            asm volatile("ld.shared.v4.b32 {%0,%1,%2,%3}, [%4];"
                         : "=r"(a[mt][0]), "=r"(a[mt][1]), "=r"(a[mt][2]), "=r"(a[mt][3])
                         : "r"(addr));
        }
        uint32_t bf[4][2];
        #pragma unroll
        for (int q = 0; q < 2; ++q) {
            // tiles: t0=(k0..7, p0..7) t1=(k8..15, p0..7) t2=(k0..7, p8..15) t3=(k8..15, p8..15)
            const int krow = k * 16 + (bt & 1) * 8 + brow;
            const int col  = wn * 32 + q * 16 + (bt >> 1) * 8;
            const uint32_t addr = sb + (uint32_t)(krow * (KSTR * 2) + col * 2);
            asm volatile("ldmatrix.sync.aligned.m8n8.x4.trans.shared.b16 "
                         "{%0,%1,%2,%3}, [%4];"
                         : "=r"(bf[q * 2][0]), "=r"(bf[q * 2][1]),
                           "=r"(bf[q * 2 + 1][0]), "=r"(bf[q * 2 + 1][1])
                         : "r"(addr));
        }
        #pragma unroll
        for (int mt = 0; mt < 4; ++mt)
            #pragma unroll
            for (int nt = 0; nt < 4; ++nt)
                mma_f16(acc[mt][nt], a[mt], bf[nt]);
    }

    // ---------------- Epilogue ----------------
    float* ob = out + ((size_t)b * OUT_) * HW_ + (size_t)h * W_;
    #pragma unroll
    for (int mt = 0; mt < 4; ++mt) {
        int o0 = wm * 64 + mt * 16 + (lane >> 2);
        #pragma unroll
        for (int nt = 0; nt < 4; ++nt) {
            int p = wn * 32 + nt * 8 + (lane & 3) * 2;
            *(float2*)(ob + (size_t)o0 * HW_ + p) =
                make_float2(acc[mt][nt][0], acc[mt][nt][1]);
            *(float2*)(ob + (size_t)(o0 + 8) * HW_ + p) =
                make_float2(acc[mt][nt][2], acc[mt][nt][3]);
        }
    }
}

// ---------------------------------------------------------------------------
extern "C" void kernel_launch(void* const* d_in, const int* in_sizes, int n_in,
                              void* d_out, int out_size)
{
    (void)in_sizes; (void)n_in; (void)out_size;
    const float* x    = (const float*)d_in[0];
    const float* colk = (const float*)d_in[1];
    const float* rowk = (const float*)d_in[2];
    const float* pw   = (const float*)d_in[3];
    float* out = (float*)d_out;

    prep_kernel<<<32, 512>>>(pw);
    cudaFuncSetAttribute(fused_kernel, cudaFuncAttributeMaxDynamicSharedMemorySize, SMEM_TOT);
    fused_kernel<<<dim3(H_, B_), 512, SMEM_TOT>>>(x, colk, rowk, out);
}